// round 1
// baseline (speedup 1.0000x reference)
#include <cuda_runtime.h>
#include <math.h>

#define HIDDEN  256
#define N_PROT  12288
#define N_MOL   6144
#define N_BATCH 32
#define MAX_SEG 1536   // binomial(6144, 1/32) mean 192; 1536 is unreachable (>90 sigma)

// Scratch (device globals: allocation-free per harness rules)
__device__ float g_Q[N_PROT * HIDDEN];
__device__ float g_K[N_MOL * HIDDEN];
__device__ float g_V[N_MOL * HIDDEN];
__device__ int   g_ss[N_BATCH];
__device__ int   g_se[N_BATCH];

// ---------------------------------------------------------------------------
// Projection GEMM: C[M,256] = X[M,256] @ W[256,256]^T + bias
// 64x64 tile, BK=16, 256 threads, 4x4 per thread.
// which: 0 -> g_Q, 1 -> g_K, 2 -> g_V
// ---------------------------------------------------------------------------
__global__ __launch_bounds__(256) void proj_kernel(
    const float* __restrict__ X, const float* __restrict__ W,
    const float* __restrict__ bias, int which)
{
    constexpr int BM = 64, BN = 64, BK = 16;
    __shared__ float Xs[BK][BM + 1];
    __shared__ float Ws[BK][BN + 1];

    float* __restrict__ C = (which == 0) ? g_Q : (which == 1) ? g_K : g_V;

    const int tx = threadIdx.x & 15;        // 0..15 (cols)
    const int ty = threadIdx.x >> 4;        // 0..15 (rows)
    const int row0 = blockIdx.x * BM;
    const int col0 = blockIdx.y * BN;

    const int lk = threadIdx.x & (BK - 1);  // 0..15 (k within tile)
    const int lr = threadIdx.x / BK;        // 0..15 (row within tile, step 16)

    float acc[4][4] = {};

    for (int k0 = 0; k0 < HIDDEN; k0 += BK) {
        #pragma unroll
        for (int r = 0; r < BM; r += 16) {
            Xs[lk][lr + r] = X[(size_t)(row0 + lr + r) * HIDDEN + k0 + lk];
            Ws[lk][lr + r] = W[(size_t)(col0 + lr + r) * HIDDEN + k0 + lk];
        }
        __syncthreads();
        #pragma unroll
        for (int kk = 0; kk < BK; kk++) {
            float a[4], b[4];
            #pragma unroll
            for (int i = 0; i < 4; i++) a[i] = Xs[kk][ty * 4 + i];
            #pragma unroll
            for (int j = 0; j < 4; j++) b[j] = Ws[kk][tx * 4 + j];
            #pragma unroll
            for (int i = 0; i < 4; i++)
                #pragma unroll
                for (int j = 0; j < 4; j++)
                    acc[i][j] = fmaf(a[i], b[j], acc[i][j]);
        }
        __syncthreads();
    }

    #pragma unroll
    for (int i = 0; i < 4; i++) {
        #pragma unroll
        for (int j = 0; j < 4; j++) {
            int c = col0 + tx * 4 + j;
            C[(size_t)(row0 + ty * 4 + i) * HIDDEN + c] = acc[i][j] + bias[c];
        }
    }
}

// ---------------------------------------------------------------------------
// Per-batch mol segment bounds (mol_batch is sorted)
// ---------------------------------------------------------------------------
__global__ void seg_kernel(const int* __restrict__ mol_batch)
{
    int b = threadIdx.x;
    if (b >= N_BATCH) return;
    int lo = 0, hi = N_MOL;
    while (lo < hi) { int mid = (lo + hi) >> 1; if (mol_batch[mid] < b) lo = mid + 1; else hi = mid; }
    g_ss[b] = lo;
    lo = 0; hi = N_MOL;
    while (lo < hi) { int mid = (lo + hi) >> 1; if (mol_batch[mid] < b + 1) lo = mid + 1; else hi = mid; }
    g_se[b] = lo;
}

// ---------------------------------------------------------------------------
// Attention: one block (256 threads) per prot row.
//  - warp-per-key dot products (float4 coalesced lane loads + shfl reduce)
//  - block softmax over the segment in shared memory
//  - single-pass write of the full 6144-wide attn row (zeros outside segment)
//  - out[i][h] = sum_j p[j] * V[s+j][h], one channel per thread
// ---------------------------------------------------------------------------
__global__ __launch_bounds__(256) void attn_kernel(
    const int* __restrict__ prot_batch,
    float* __restrict__ out, float* __restrict__ attn)
{
    const int i    = blockIdx.x;
    const int tid  = threadIdx.x;
    const int warp = tid >> 5;
    const int lane = tid & 31;

    __shared__ float sc[MAX_SEG];
    __shared__ float red[8];

    const int b = prot_batch[i];
    const int s = g_ss[b];
    const int e = g_se[b];
    int m = e - s;
    if (m > MAX_SEG) m = MAX_SEG;   // unreachable; safety

    if (m > 0) {
        // Q row in registers (each lane holds 8 of the 256 dims)
        const float4* Qrow = (const float4*)(g_Q + (size_t)i * HIDDEN);
        const float4 qa = Qrow[lane];
        const float4 qb = Qrow[32 + lane];

        // scores: one key per warp per iteration
        for (int j = warp; j < m; j += 8) {
            const float4* Krow = (const float4*)(g_K + (size_t)(s + j) * HIDDEN);
            float4 ka = Krow[lane];
            float4 kb = Krow[32 + lane];
            float d = qa.x * ka.x + qa.y * ka.y + qa.z * ka.z + qa.w * ka.w
                    + qb.x * kb.x + qb.y * kb.y + qb.z * kb.z + qb.w * kb.w;
            #pragma unroll
            for (int off = 16; off; off >>= 1)
                d += __shfl_xor_sync(0xffffffffu, d, off);
            if (lane == 0) sc[j] = d * 0.0625f;   // 1/sqrt(256)
        }
        __syncthreads();

        // block max
        float mx = -INFINITY;
        for (int j = tid; j < m; j += 256) mx = fmaxf(mx, sc[j]);
        #pragma unroll
        for (int off = 16; off; off >>= 1)
            mx = fmaxf(mx, __shfl_xor_sync(0xffffffffu, mx, off));
        if (lane == 0) red[warp] = mx;
        __syncthreads();
        mx = red[0];
        #pragma unroll
        for (int w = 1; w < 8; w++) mx = fmaxf(mx, red[w]);

        // exp + block sum
        float sum = 0.f;
        for (int j = tid; j < m; j += 256) {
            float v = __expf(sc[j] - mx);
            sc[j] = v;
            sum += v;
        }
        #pragma unroll
        for (int off = 16; off; off >>= 1)
            sum += __shfl_xor_sync(0xffffffffu, sum, off);
        __syncthreads();              // all reads of red (max) done
        if (lane == 0) red[warp] = sum;
        __syncthreads();
        sum = 0.f;
        #pragma unroll
        for (int w = 0; w < 8; w++) sum += red[w];
        const float inv = 1.f / sum;
        for (int j = tid; j < m; j += 256) sc[j] *= inv;
        __syncthreads();
    }

    // Write full attn row (zeros outside [s,e)), float4-vectorized
    float4* arow4 = (float4*)(attn + (size_t)i * N_MOL);
    for (int c4 = tid; c4 < N_MOL / 4; c4 += 256) {
        const int c = c4 * 4;
        float4 v;
        v.x = (c + 0 >= s && c + 0 < e) ? sc[c + 0 - s] : 0.f;
        v.y = (c + 1 >= s && c + 1 < e) ? sc[c + 1 - s] : 0.f;
        v.z = (c + 2 >= s && c + 2 < e) ? sc[c + 2 - s] : 0.f;
        v.w = (c + 3 >= s && c + 3 < e) ? sc[c + 3 - s] : 0.f;
        arow4[c4] = v;
    }

    // out[i][h] = sum_j p[j] * V[s+j][h] ; one channel per thread
    float acc = 0.f;
    for (int j = 0; j < m; j++)
        acc = fmaf(sc[j], g_V[(size_t)(s + j) * HIDDEN + tid], acc);
    out[(size_t)i * HIDDEN + tid] = acc;
}

// ---------------------------------------------------------------------------
extern "C" void kernel_launch(void* const* d_in, const int* in_sizes, int n_in,
                              void* d_out, int out_size)
{
    const float* prot_embed = (const float*)d_in[0];
    const float* mol_embed  = (const float*)d_in[1];
    const int*   prot_batch = (const int*)d_in[2];
    const int*   mol_batch  = (const int*)d_in[3];
    const float* Wq = (const float*)d_in[4];
    const float* bq = (const float*)d_in[5];
    const float* Wk = (const float*)d_in[6];
    const float* bk = (const float*)d_in[7];
    const float* Wv = (const float*)d_in[8];
    const float* bv = (const float*)d_in[9];

    float* out  = (float*)d_out;                              // [N_PROT, HIDDEN]
    float* attn = (float*)d_out + (size_t)N_PROT * HIDDEN;    // [N_PROT, N_MOL]

    // Projections
    {
        dim3 gq(N_PROT / 64, HIDDEN / 64);
        dim3 gm(N_MOL / 64, HIDDEN / 64);
        proj_kernel<<<gq, 256>>>(prot_embed, Wq, bq, 0);
        proj_kernel<<<gm, 256>>>(mol_embed,  Wk, bk, 1);
        proj_kernel<<<gm, 256>>>(mol_embed,  Wv, bv, 2);
    }

    // Segment bounds
    seg_kernel<<<1, 32>>>(mol_batch);

    // Attention + outputs
    attn_kernel<<<N_PROT, 256>>>(prot_batch, out, attn);
}